// round 2
// baseline (speedup 1.0000x reference)
#include <cuda_runtime.h>

typedef unsigned long long ull;

#define HH 192
#define BB 16
#define NPIX (BB*2*HH*HH)

// ---------- packed f32x2 helpers (sm_103a) ----------
__device__ __forceinline__ ull pk2(float x, float y){ ull r; asm("mov.b64 %0,{%1,%2};":"=l"(r):"f"(x),"f"(y)); return r; }
__device__ __forceinline__ ull dup2(float x){ return pk2(x,x); }
__device__ __forceinline__ void unpk2(ull v, float&x, float&y){ asm("mov.b64 {%0,%1},%2;":"=f"(x),"=f"(y):"l"(v)); }
__device__ __forceinline__ ull ffma2(ull a, ull b, ull c){ ull d; asm("fma.rn.f32x2 %0,%1,%2,%3;":"=l"(d):"l"(a),"l"(b),"l"(c)); return d; }
__device__ __forceinline__ ull fmul2(ull a, ull b){ ull d; asm("mul.rn.f32x2 %0,%1,%2;":"=l"(d):"l"(a),"l"(b)); return d; }
__device__ __forceinline__ ull fadd2(ull a, ull b){ ull d; asm("add.rn.f32x2 %0,%1,%2;":"=l"(d):"l"(a),"l"(b)); return d; }

// ---------- packed constants ----------
struct ConstBlob {
  ull k[200];
  ull w0[24];    // [u*12+i]
  ull b0[2];
  ull w1[26];    // [u*13+i]
  ull b1[2];
  ull wf[14];
  ull bf;
  ull gw0[2][2]; // [off-1][u]
  ull gw1[2][2];
  ull gwf[2];
};

__constant__ ConstBlob cb;
__device__ ConstBlob g_stage;
__device__ float g_uh[NPIX];
__device__ float g_ua[NPIX];
__device__ float g_ub[NPIX];

__global__ void prep_kernel(const float* __restrict__ kern,
                            const float* __restrict__ w0, const float* __restrict__ b0,
                            const float* __restrict__ w1, const float* __restrict__ b1,
                            const float* __restrict__ wf, const float* __restrict__ bf)
{
  int t = threadIdx.x;
  const double dDX = 0.0327249;
  const float s1 = (float)(1.0/dDX);
  const float s2 = (float)(1.0/(dDX*dDX));
  const float sc[6] = {1.f, s1, s1, s2, s2, s2};
  if (t < 200) {
    int d = t/25, r = (t%25)/5, c = t%5;
    float v;
    if (d < 6)       v =  kern[d*25 + r*5 + c] * sc[d];
    else if (d == 6) v = -kern[25 + r*5 + (4-c)] * sc[1];   // -flip along width of fd01
    else             v = -kern[50 + (4-r)*5 + c] * sc[2];   // -flip along height of fd10
    g_stage.k[t] = dup2(v);
  }
  if (t == 0) {
    for (int u = 0; u < 2; u++) {
      for (int i = 0; i < 12; i++) g_stage.w0[u*12+i] = pk2(w0[u*12+i], w0[24+u*12+i]);
      g_stage.b0[u] = pk2(b0[u], b0[2+u]);
      for (int i = 0; i < 13; i++) g_stage.w1[u*13+i] = pk2(w1[u*13+i], w1[26+u*13+i]);
      g_stage.b1[u] = pk2(b1[u], b1[2+u]);
    }
    for (int i = 0; i < 14; i++) g_stage.wf[i] = pk2(wf[i], wf[14+i]);
    g_stage.bf = pk2(bf[0], bf[1]);
    for (int o = 0; o < 2; o++) {
      for (int u = 0; u < 2; u++) {
        g_stage.gw0[o][u] = pk2(w0[u*12 + 1 + o], w0[24 + u*12 + 7 + o]);
        g_stage.gw1[o][u] = pk2(w1[u*13 + 1 + o], w1[26 + u*13 + 7 + o]);
      }
      g_stage.gwf[o] = pk2(wf[1 + o], wf[14 + 7 + o]);
    }
  }
}

// SymNet + gradient + upwind + final poly for one pixel (packed channels in acc lanes).
__device__ __forceinline__ void poly_pixel(const ull acc[8], float& ua0, float& ua1)
{
  float X[12];
  #pragma unroll
  for (int d = 0; d < 6; d++) unpk2(acc[d], X[d], X[6+d]);
  float f01x, f01y, f10x, f10y;
  unpk2(acc[6], f01x, f01y);
  unpk2(acc[7], f10x, f10y);

  // linear parts at base (lanes = poly k0,k1)
  ull p2 = cb.b0[0], q2 = cb.b0[1], rl = cb.b1[0], sl = cb.b1[1], ol = cb.bf;
  #pragma unroll
  for (int i = 0; i < 12; i++) {
    ull xd = dup2(X[i]);
    p2 = ffma2(cb.w0[i],    xd, p2);
    q2 = ffma2(cb.w0[12+i], xd, q2);
    rl = ffma2(cb.w1[i],    xd, rl);
    sl = ffma2(cb.w1[13+i], xd, sl);
    ol = ffma2(cb.wf[i],    xd, ol);
  }
  ull m1 = fmul2(p2, q2);
  ull r2 = ffma2(cb.w1[12], m1, rl);
  ull s2 = ffma2(cb.w1[25], m1, sl);

  // analytic gradient at base: d(poly_k)/dX[k*6+off], off=1,2
  ull g2[2];
  #pragma unroll
  for (int o = 0; o < 2; o++) {
    ull dm1 = fadd2(fmul2(q2, cb.gw0[o][0]), fmul2(p2, cb.gw0[o][1]));
    ull dr  = ffma2(cb.w1[12], dm1, cb.gw1[o][0]);
    ull ds  = ffma2(cb.w1[25], dm1, cb.gw1[o][1]);
    ull dm2 = fadd2(fmul2(s2, dr), fmul2(r2, ds));
    ull g   = ffma2(cb.wf[12], dm1, cb.gwf[o]);
    g2[o]   = ffma2(cb.wf[13], dm2, g);
  }
  float g01a, g01b, g10a, g10b;
  unpk2(g2[0], g01a, g01b);
  unpk2(g2[1], g10a, g10b);

  // upwind deltas (0 if keep base, else flipped - base)
  float d1 = (g01a > 0.f) ? 0.f : (f01x - X[1]);
  float d7 = (g01b > 0.f) ? 0.f : (f01y - X[7]);
  float d2 = (g10a > 0.f) ? 0.f : (f10x - X[2]);
  float d8 = (g10b > 0.f) ? 0.f : (f10y - X[8]);
  ull D1 = dup2(d1), D2 = dup2(d2), D7 = dup2(d7), D8 = dup2(d8);

  // delta-update linear parts to Xsel, finish poly
  p2 = ffma2(cb.w0[1], D1, ffma2(cb.w0[2], D2, ffma2(cb.w0[7], D7, ffma2(cb.w0[8], D8, p2))));
  q2 = ffma2(cb.w0[13], D1, ffma2(cb.w0[14], D2, ffma2(cb.w0[19], D7, ffma2(cb.w0[20], D8, q2))));
  rl = ffma2(cb.w1[1], D1, ffma2(cb.w1[2], D2, ffma2(cb.w1[7], D7, ffma2(cb.w1[8], D8, rl))));
  sl = ffma2(cb.w1[14], D1, ffma2(cb.w1[15], D2, ffma2(cb.w1[20], D7, ffma2(cb.w1[21], D8, sl))));
  ol = ffma2(cb.wf[1], D1, ffma2(cb.wf[2], D2, ffma2(cb.wf[7], D7, ffma2(cb.wf[8], D8, ol))));

  m1 = fmul2(p2, q2);
  r2 = ffma2(cb.w1[12], m1, rl);
  s2 = ffma2(cb.w1[25], m1, sl);
  ull m2 = fmul2(r2, s2);
  ull o2 = ffma2(cb.wf[12], m1, ol);
  o2 = ffma2(cb.wf[13], m2, o2);
  unpk2(o2, ua0, ua1);
}

// out = ubase + coef * rhs(ueval); each thread computes 2 vertically-adjacent pixels
__global__ __launch_bounds__(256, 3)
void rhs_step(const float* __restrict__ ue, const float* __restrict__ ub,
              float coef, float* __restrict__ out)
{
  __shared__ ull tile[20][36];   // (c0,c1) packed, pixel rows h0-2 .. h0+17

  const int tx = threadIdx.x, ty = threadIdx.y;   // 32 x 8
  const int tid = ty*32 + tx;
  const int w0_ = blockIdx.x*32, h0 = blockIdx.y*16, b = blockIdx.z;

  const float* u0 = ue + (size_t)b*2*HH*HH;
  const float* u1 = u0 + HH*HH;

  #pragma unroll
  for (int e = tid; e < 20*36; e += 256) {
    int r = e/36, c = e%36;
    int h = h0 + r - 2; if (h < 0) h += HH; if (h >= HH) h -= HH;
    int w = w0_ + c - 2; if (w < 0) w += HH; if (w >= HH) w -= HH;
    tile[r][c] = pk2(u0[h*HH+w], u1[h*HH+w]);
  }
  __syncthreads();

  // pixel rows p0 = h0 + 2ty, p1 = p0+1; windows = tile rows [2ty..2ty+4], [2ty+1..2ty+5]
  ull acc0[8], acc1[8];
  #pragma unroll
  for (int d = 0; d < 8; d++) { acc0[d] = 0ull; acc1[d] = 0ull; }

  const int ry = 2*ty;
  #pragma unroll
  for (int i = 0; i < 6; i++) {
    ull w[5];
    #pragma unroll
    for (int j = 0; j < 5; j++) w[j] = tile[ry + i][tx + j];
    if (i < 5) {
      #pragma unroll
      for (int j = 0; j < 5; j++)
        #pragma unroll
        for (int d = 0; d < 8; d++)
          acc0[d] = ffma2(cb.k[d*25 + i*5 + j], w[j], acc0[d]);
    }
    if (i >= 1) {
      #pragma unroll
      for (int j = 0; j < 5; j++)
        #pragma unroll
        for (int d = 0; d < 8; d++)
          acc1[d] = ffma2(cb.k[d*25 + (i-1)*5 + j], w[j], acc1[d]);
    }
  }

  float a0, a1, b0_, b1_;
  poly_pixel(acc0, a0, a1);
  poly_pixel(acc1, b0_, b1_);

  const int h = h0 + ry, w = w0_ + tx;
  const size_t i0 = ((size_t)(b*2))*HH*HH + (size_t)h*HH + w;
  out[i0]              = ub[i0]              + coef*a0;
  out[i0 + HH*HH]      = ub[i0 + HH*HH]      + coef*a1;
  out[i0 + HH]         = ub[i0 + HH]         + coef*b0_;
  out[i0 + HH + HH*HH] = ub[i0 + HH + HH*HH] + coef*b1_;
}

extern "C" void kernel_launch(void* const* d_in, const int* in_sizes, int n_in,
                              void* d_out, int out_size)
{
  (void)in_sizes; (void)n_in; (void)out_size;
  const float* init = (const float*)d_in[0];
  const float* kern = (const float*)d_in[1];
  const float* w0   = (const float*)d_in[2];
  const float* b0   = (const float*)d_in[3];
  const float* w1   = (const float*)d_in[4];
  const float* b1   = (const float*)d_in[5];
  const float* wf   = (const float*)d_in[6];
  const float* bf   = (const float*)d_in[7];
  float* out = (float*)d_out;

  void *puh, *pua, *pub, *pstage;
  cudaGetSymbolAddress(&puh, g_uh);
  cudaGetSymbolAddress(&pua, g_ua);
  cudaGetSymbolAddress(&pub, g_ub);
  cudaGetSymbolAddress(&pstage, g_stage);

  prep_kernel<<<1, 256>>>(kern, w0, b0, w1, b1, wf, bf);
  cudaMemcpyToSymbolAsync(cb, pstage, sizeof(ConstBlob), 0, cudaMemcpyDeviceToDevice, 0);

  dim3 grid(HH/32, HH/16, BB);
  dim3 block(32, 8);

  const float DT = 0.2f;
  const float* ucur = init;
  for (int s = 0; s < 5; s++) {
    float* un = (s == 4) ? out : ((s & 1) ? (float*)pub : (float*)pua);
    rhs_step<<<grid, block>>>(ucur, ucur, DT*0.5f, (float*)puh);
    rhs_step<<<grid, block>>>((float*)puh, ucur, DT, un);
    ucur = un;
  }
}

// round 3
// speedup vs baseline: 2.9105x; 2.9105x over previous
#include <cuda_runtime.h>

typedef unsigned long long ull;

#define HH 192
#define BB 16
#define NPIX (BB*2*HH*HH)

// ---------- packed f32x2 helpers (sm_103a) ----------
__device__ __forceinline__ ull pk2(float x, float y){ ull r; asm("mov.b64 %0,{%1,%2};":"=l"(r):"f"(x),"f"(y)); return r; }
__device__ __forceinline__ ull dup2(float x){ return pk2(x,x); }
__device__ __forceinline__ void unpk2(ull v, float&x, float&y){ asm("mov.b64 {%0,%1},%2;":"=f"(x),"=f"(y):"l"(v)); }
__device__ __forceinline__ ull ffma2(ull a, ull b, ull c){ ull d; asm("fma.rn.f32x2 %0,%1,%2,%3;":"=l"(d):"l"(a),"l"(b),"l"(c)); return d; }
__device__ __forceinline__ ull fmul2(ull a, ull b){ ull d; asm("mul.rn.f32x2 %0,%1,%2;":"=l"(d):"l"(a),"l"(b)); return d; }
__device__ __forceinline__ ull fadd2(ull a, ull b){ ull d; asm("add.rn.f32x2 %0,%1,%2;":"=l"(d):"l"(a),"l"(b)); return d; }

// ---------- packed constants ----------
// k[]: 6 stencils (fd00,fd01,fd10,fd02,fd11,fd20) scaled by dx^-ord, duplicated lanes.
// The flipped stencils for f01/f10 reuse k[1]/k[2] with mirrored window indices.
struct ConstBlob {
  ull k[150];
  ull w0[24];    // [u*12+i]
  ull b0[2];
  ull w1[26];    // [u*13+i]
  ull b1[2];
  ull wf[14];
  ull bf;
  ull gw0[2][2]; // [off-1][u]
  ull gw1[2][2];
  ull gwf[2];
};

__constant__ ConstBlob cb;
__device__ ConstBlob g_stage;
__device__ float g_uh[NPIX];
__device__ float g_ua[NPIX];
__device__ float g_ub[NPIX];

__global__ void prep_kernel(const float* __restrict__ kern,
                            const float* __restrict__ w0, const float* __restrict__ b0,
                            const float* __restrict__ w1, const float* __restrict__ b1,
                            const float* __restrict__ wf, const float* __restrict__ bf)
{
  int t = threadIdx.x;
  const double dDX = 0.0327249;
  const float s1 = (float)(1.0/dDX);
  const float s2 = (float)(1.0/(dDX*dDX));
  const float sc[6] = {1.f, s1, s1, s2, s2, s2};
  if (t < 150) {
    int d = t/25, r = (t%25)/5, c = t%5;
    g_stage.k[t] = dup2(kern[d*25 + r*5 + c] * sc[d]);
  }
  if (t == 0) {
    for (int u = 0; u < 2; u++) {
      for (int i = 0; i < 12; i++) g_stage.w0[u*12+i] = pk2(w0[u*12+i], w0[24+u*12+i]);
      g_stage.b0[u] = pk2(b0[u], b0[2+u]);
      for (int i = 0; i < 13; i++) g_stage.w1[u*13+i] = pk2(w1[u*13+i], w1[26+u*13+i]);
      g_stage.b1[u] = pk2(b1[u], b1[2+u]);
    }
    for (int i = 0; i < 14; i++) g_stage.wf[i] = pk2(wf[i], wf[14+i]);
    g_stage.bf = pk2(bf[0], bf[1]);
    for (int o = 0; o < 2; o++) {
      for (int u = 0; u < 2; u++) {
        g_stage.gw0[o][u] = pk2(w0[u*12 + 1 + o], w0[24 + u*12 + 7 + o]);
        g_stage.gw1[o][u] = pk2(w1[u*13 + 1 + o], w1[26 + u*13 + 7 + o]);
      }
      g_stage.gwf[o] = pk2(wf[1 + o], wf[14 + 7 + o]);
    }
  }
}

// out = ubase + coef * rhs(ueval); 1 pixel/thread, 32x8 blocks
__global__ __launch_bounds__(256, 5)
void rhs_step(const float* __restrict__ ue, const float* __restrict__ ub,
              float coef, float* __restrict__ out)
{
  __shared__ ull tile[12][36];   // (c0,c1) packed, rows h0-2 .. h0+9

  const int tx = threadIdx.x, ty = threadIdx.y;
  const int tid = ty*32 + tx;
  const int w0_ = blockIdx.x*32, h0 = blockIdx.y*8, b = blockIdx.z;

  const float* u0 = ue + (size_t)b*2*HH*HH;
  const float* u1 = u0 + HH*HH;

  #pragma unroll
  for (int e = tid; e < 12*36; e += 256) {
    int r = e/36, c = e%36;
    int h = h0 + r - 2; if (h < 0) h += HH; if (h >= HH) h -= HH;
    int w = w0_ + c - 2; if (w < 0) w += HH; if (w >= HH) w -= HH;
    tile[r][c] = pk2(u0[h*HH+w], u1[h*HH+w]);
  }
  __syncthreads();

  // ---- 6 base correlations + 2 mirrored (sharing constants with d=1,2) ----
  ull acc[6], t6 = 0ull, t7 = 0ull;
  #pragma unroll
  for (int d = 0; d < 6; d++) acc[d] = 0ull;
  #pragma unroll
  for (int i = 0; i < 5; i++) {
    ull w[5];
    #pragma unroll
    for (int j = 0; j < 5; j++) w[j] = tile[ty+i][tx+j];
    #pragma unroll
    for (int j = 0; j < 5; j++) {
      #pragma unroll
      for (int d = 0; d < 6; d++) acc[d] = ffma2(cb.k[d*25 + i*5 + j], w[j], acc[d]);
      // f01 = -sum k01[i][j]*w[i][4-j]   (flip along width, negated)
      t6 = ffma2(cb.k[25 + i*5 + j], w[4-j], t6);
      // f10 = -sum k10[i][j]*w[4-i][j]   (flip along height, negated)
      t7 = ffma2(cb.k[50 + (4-i)*5 + j], w[j], t7);
    }
  }

  float X[12];
  #pragma unroll
  for (int d = 0; d < 6; d++) unpk2(acc[d], X[d], X[6+d]);
  float n6x, n6y, n7x, n7y;
  unpk2(t6, n6x, n6y);   // f01 = -n6
  unpk2(t7, n7x, n7y);   // f10 = -n7

  // ---- poly linear parts at base (lanes = poly k0,k1) ----
  ull p2 = cb.b0[0], q2 = cb.b0[1], rl = cb.b1[0], sl = cb.b1[1], ol = cb.bf;
  #pragma unroll
  for (int i = 0; i < 12; i++) {
    ull xd = dup2(X[i]);
    p2 = ffma2(cb.w0[i],    xd, p2);
    q2 = ffma2(cb.w0[12+i], xd, q2);
    rl = ffma2(cb.w1[i],    xd, rl);
    sl = ffma2(cb.w1[13+i], xd, sl);
    ol = ffma2(cb.wf[i],    xd, ol);
  }
  ull m1 = fmul2(p2, q2);
  ull r2 = ffma2(cb.w1[12], m1, rl);
  ull s2 = ffma2(cb.w1[25], m1, sl);

  // ---- analytic gradient at base: d(poly_k)/dX[k*6+off], off=1,2 ----
  ull g2[2];
  #pragma unroll
  for (int o = 0; o < 2; o++) {
    ull dm1 = fadd2(fmul2(q2, cb.gw0[o][0]), fmul2(p2, cb.gw0[o][1]));
    ull dr  = ffma2(cb.w1[12], dm1, cb.gw1[o][0]);
    ull ds  = ffma2(cb.w1[25], dm1, cb.gw1[o][1]);
    ull dm2 = fadd2(fmul2(s2, dr), fmul2(r2, ds));
    ull g   = ffma2(cb.wf[12], dm1, cb.gwf[o]);
    g2[o]   = ffma2(cb.wf[13], dm2, g);
  }
  float g01a, g01b, g10a, g10b;
  unpk2(g2[0], g01a, g01b);
  unpk2(g2[1], g10a, g10b);

  // upwind deltas (0 if keep base, else flipped - base); flipped = -n
  float d1 = (g01a > 0.f) ? 0.f : (-n6x - X[1]);
  float d7 = (g01b > 0.f) ? 0.f : (-n6y - X[7]);
  float d2 = (g10a > 0.f) ? 0.f : (-n7x - X[2]);
  float d8 = (g10b > 0.f) ? 0.f : (-n7y - X[8]);
  ull D1 = dup2(d1), D2 = dup2(d2), D7 = dup2(d7), D8 = dup2(d8);

  // ---- delta-update linear parts to Xsel, finish poly ----
  p2 = ffma2(cb.w0[1], D1, ffma2(cb.w0[2], D2, ffma2(cb.w0[7], D7, ffma2(cb.w0[8], D8, p2))));
  q2 = ffma2(cb.w0[13], D1, ffma2(cb.w0[14], D2, ffma2(cb.w0[19], D7, ffma2(cb.w0[20], D8, q2))));
  rl = ffma2(cb.w1[1], D1, ffma2(cb.w1[2], D2, ffma2(cb.w1[7], D7, ffma2(cb.w1[8], D8, rl))));
  sl = ffma2(cb.w1[14], D1, ffma2(cb.w1[15], D2, ffma2(cb.w1[20], D7, ffma2(cb.w1[21], D8, sl))));
  ol = ffma2(cb.wf[1], D1, ffma2(cb.wf[2], D2, ffma2(cb.wf[7], D7, ffma2(cb.wf[8], D8, ol))));

  m1 = fmul2(p2, q2);
  r2 = ffma2(cb.w1[12], m1, rl);
  s2 = ffma2(cb.w1[25], m1, sl);
  ull m2 = fmul2(r2, s2);
  ull o2 = ffma2(cb.wf[12], m1, ol);
  o2 = ffma2(cb.wf[13], m2, o2);

  float ua0, ua1;
  unpk2(o2, ua0, ua1);

  const int h = h0 + ty, w = w0_ + tx;
  const size_t i0 = ((size_t)(b*2))*HH*HH + (size_t)h*HH + w;
  out[i0]         = ub[i0]         + coef*ua0;
  out[i0 + HH*HH] = ub[i0 + HH*HH] + coef*ua1;
}

extern "C" void kernel_launch(void* const* d_in, const int* in_sizes, int n_in,
                              void* d_out, int out_size)
{
  (void)in_sizes; (void)n_in; (void)out_size;
  const float* init = (const float*)d_in[0];
  const float* kern = (const float*)d_in[1];
  const float* w0   = (const float*)d_in[2];
  const float* b0   = (const float*)d_in[3];
  const float* w1   = (const float*)d_in[4];
  const float* b1   = (const float*)d_in[5];
  const float* wf   = (const float*)d_in[6];
  const float* bf   = (const float*)d_in[7];
  float* out = (float*)d_out;

  void *puh, *pua, *pub, *pstage;
  cudaGetSymbolAddress(&puh, g_uh);
  cudaGetSymbolAddress(&pua, g_ua);
  cudaGetSymbolAddress(&pub, g_ub);
  cudaGetSymbolAddress(&pstage, g_stage);

  prep_kernel<<<1, 256>>>(kern, w0, b0, w1, b1, wf, bf);
  cudaMemcpyToSymbolAsync(cb, pstage, sizeof(ConstBlob), 0, cudaMemcpyDeviceToDevice, 0);

  dim3 grid(HH/32, HH/8, BB);
  dim3 block(32, 8);

  const float DT = 0.2f;
  const float* ucur = init;
  for (int s = 0; s < 5; s++) {
    float* un = (s == 4) ? out : ((s & 1) ? (float*)pub : (float*)pua);
    rhs_step<<<grid, block>>>(ucur, ucur, DT*0.5f, (float*)puh);
    rhs_step<<<grid, block>>>((float*)puh, ucur, DT, un);
    ucur = un;
  }
}

// round 4
// speedup vs baseline: 2.9968x; 1.0297x over previous
#include <cuda_runtime.h>

typedef unsigned long long ull;

#define HH 192
#define BB 16
#define NPIX (BB*2*HH*HH)

// ---------- packed f32x2 helpers (sm_103a) ----------
__device__ __forceinline__ ull pk2(float x, float y){ ull r; asm("mov.b64 %0,{%1,%2};":"=l"(r):"f"(x),"f"(y)); return r; }
__device__ __forceinline__ ull dup2(float x){ return pk2(x,x); }
__device__ __forceinline__ void unpk2(ull v, float&x, float&y){ asm("mov.b64 {%0,%1},%2;":"=f"(x),"=f"(y):"l"(v)); }
__device__ __forceinline__ ull ffma2(ull a, ull b, ull c){ ull d; asm("fma.rn.f32x2 %0,%1,%2,%3;":"=l"(d):"l"(a),"l"(b),"l"(c)); return d; }
__device__ __forceinline__ ull fmul2(ull a, ull b){ ull d; asm("mul.rn.f32x2 %0,%1,%2;":"=l"(d):"l"(a),"l"(b)); return d; }
__device__ __forceinline__ ull fadd2(ull a, ull b){ ull d; asm("add.rn.f32x2 %0,%1,%2;":"=l"(d):"l"(a),"l"(b)); return d; }

// ---------- packed constants ----------
// k[]: 6 stencils (fd00,fd01,fd10,fd02,fd11,fd20) scaled by dx^-ord, duplicated lanes.
// Flipped stencils for f01/f10 reuse k[1]/k[2] with mirrored window indices.
struct ConstBlob {
  ull k[150];
  ull w0[24];    // [u*12+i]
  ull b0[2];
  ull w1[26];    // [u*13+i]
  ull b1[2];
  ull wf[14];
  ull bf;
  ull gw0[2][2]; // [off-1][u]
  ull gw1[2][2];
  ull gwf[2];
};

__constant__ ConstBlob cb;
__device__ ConstBlob g_stage;
__device__ float g_uh[NPIX];
__device__ float g_ua[NPIX];
__device__ float g_ub[NPIX];

__global__ void prep_kernel(const float* __restrict__ kern,
                            const float* __restrict__ w0, const float* __restrict__ b0,
                            const float* __restrict__ w1, const float* __restrict__ b1,
                            const float* __restrict__ wf, const float* __restrict__ bf)
{
  int t = threadIdx.x;
  const double dDX = 0.0327249;
  const float s1 = (float)(1.0/dDX);
  const float s2 = (float)(1.0/(dDX*dDX));
  const float sc[6] = {1.f, s1, s1, s2, s2, s2};
  if (t < 150) {
    int d = t/25, r = (t%25)/5, c = t%5;
    g_stage.k[t] = dup2(kern[d*25 + r*5 + c] * sc[d]);
  }
  if (t == 0) {
    for (int u = 0; u < 2; u++) {
      for (int i = 0; i < 12; i++) g_stage.w0[u*12+i] = pk2(w0[u*12+i], w0[24+u*12+i]);
      g_stage.b0[u] = pk2(b0[u], b0[2+u]);
      for (int i = 0; i < 13; i++) g_stage.w1[u*13+i] = pk2(w1[u*13+i], w1[26+u*13+i]);
      g_stage.b1[u] = pk2(b1[u], b1[2+u]);
    }
    for (int i = 0; i < 14; i++) g_stage.wf[i] = pk2(wf[i], wf[14+i]);
    g_stage.bf = pk2(bf[0], bf[1]);
    for (int o = 0; o < 2; o++) {
      for (int u = 0; u < 2; u++) {
        g_stage.gw0[o][u] = pk2(w0[u*12 + 1 + o], w0[24 + u*12 + 7 + o]);
        g_stage.gw1[o][u] = pk2(w1[u*13 + 1 + o], w1[26 + u*13 + 7 + o]);
      }
      g_stage.gwf[o] = pk2(wf[1 + o], wf[14 + 7 + o]);
    }
  }
}

// out = ubase + coef * rhs(ueval); 1 pixel/thread, 32x6 blocks, 7 blocks/SM
__global__ __launch_bounds__(192, 7)
void rhs_step(const float* __restrict__ ue, const float* __restrict__ ub,
              float coef, float* __restrict__ out)
{
  __shared__ ull tile[10][36];   // (c0,c1) packed, rows h0-2 .. h0+7

  const int tx = threadIdx.x, ty = threadIdx.y;
  const int tid = ty*32 + tx;
  const int w0_ = blockIdx.x*32, h0 = blockIdx.y*6, b = blockIdx.z;

  const float* u0 = ue + (size_t)b*2*HH*HH;
  const float* u1 = u0 + HH*HH;

  #pragma unroll
  for (int e = tid; e < 10*36; e += 192) {
    int r = e/36, c = e%36;
    int h = h0 + r - 2; if (h < 0) h += HH; if (h >= HH) h -= HH;
    int w = w0_ + c - 2; if (w < 0) w += HH; if (w >= HH) w -= HH;
    tile[r][c] = pk2(u0[h*HH+w], u1[h*HH+w]);
  }
  __syncthreads();

  // ---- 6 base correlations + 2 mirrored (sharing constants with d=1,2) ----
  ull acc[6], t6 = 0ull, t7 = 0ull;
  #pragma unroll
  for (int d = 0; d < 6; d++) acc[d] = 0ull;
  #pragma unroll
  for (int i = 0; i < 5; i++) {
    ull w[5];
    #pragma unroll
    for (int j = 0; j < 5; j++) w[j] = tile[ty+i][tx+j];
    #pragma unroll
    for (int j = 0; j < 5; j++) {
      #pragma unroll
      for (int d = 0; d < 6; d++) acc[d] = ffma2(cb.k[d*25 + i*5 + j], w[j], acc[d]);
      // f01 = -sum k01[i][j]*w[i][4-j]   (flip along width, negated)
      t6 = ffma2(cb.k[25 + i*5 + j], w[4-j], t6);
      // f10 = -sum k10[i][j]*w[4-i][j]   (flip along height, negated)
      t7 = ffma2(cb.k[50 + (4-i)*5 + j], w[j], t7);
    }
  }

  float X[12];
  #pragma unroll
  for (int d = 0; d < 6; d++) unpk2(acc[d], X[d], X[6+d]);
  float n6x, n6y, n7x, n7y;
  unpk2(t6, n6x, n6y);   // f01 = -n6
  unpk2(t7, n7x, n7y);   // f10 = -n7

  // ---- poly linear parts at base (lanes = poly k0,k1) ----
  ull p2 = cb.b0[0], q2 = cb.b0[1], rl = cb.b1[0], sl = cb.b1[1], ol = cb.bf;
  #pragma unroll
  for (int i = 0; i < 12; i++) {
    ull xd = dup2(X[i]);
    p2 = ffma2(cb.w0[i],    xd, p2);
    q2 = ffma2(cb.w0[12+i], xd, q2);
    rl = ffma2(cb.w1[i],    xd, rl);
    sl = ffma2(cb.w1[13+i], xd, sl);
    ol = ffma2(cb.wf[i],    xd, ol);
  }
  ull m1 = fmul2(p2, q2);
  ull r2 = ffma2(cb.w1[12], m1, rl);
  ull s2 = ffma2(cb.w1[25], m1, sl);

  // ---- analytic gradient at base: d(poly_k)/dX[k*6+off], off=1,2 ----
  ull g2[2];
  #pragma unroll
  for (int o = 0; o < 2; o++) {
    ull dm1 = fadd2(fmul2(q2, cb.gw0[o][0]), fmul2(p2, cb.gw0[o][1]));
    ull dr  = ffma2(cb.w1[12], dm1, cb.gw1[o][0]);
    ull ds  = ffma2(cb.w1[25], dm1, cb.gw1[o][1]);
    ull dm2 = fadd2(fmul2(s2, dr), fmul2(r2, ds));
    ull g   = ffma2(cb.wf[12], dm1, cb.gwf[o]);
    g2[o]   = ffma2(cb.wf[13], dm2, g);
  }
  float g01a, g01b, g10a, g10b;
  unpk2(g2[0], g01a, g01b);
  unpk2(g2[1], g10a, g10b);

  // upwind deltas (0 if keep base, else flipped - base); flipped = -n
  float d1 = (g01a > 0.f) ? 0.f : (-n6x - X[1]);
  float d7 = (g01b > 0.f) ? 0.f : (-n6y - X[7]);
  float d2 = (g10a > 0.f) ? 0.f : (-n7x - X[2]);
  float d8 = (g10b > 0.f) ? 0.f : (-n7y - X[8]);
  ull D1 = dup2(d1), D2 = dup2(d2), D7 = dup2(d7), D8 = dup2(d8);

  // ---- delta-update linear parts to Xsel, finish poly ----
  p2 = ffma2(cb.w0[1], D1, ffma2(cb.w0[2], D2, ffma2(cb.w0[7], D7, ffma2(cb.w0[8], D8, p2))));
  q2 = ffma2(cb.w0[13], D1, ffma2(cb.w0[14], D2, ffma2(cb.w0[19], D7, ffma2(cb.w0[20], D8, q2))));
  rl = ffma2(cb.w1[1], D1, ffma2(cb.w1[2], D2, ffma2(cb.w1[7], D7, ffma2(cb.w1[8], D8, rl))));
  sl = ffma2(cb.w1[14], D1, ffma2(cb.w1[15], D2, ffma2(cb.w1[20], D7, ffma2(cb.w1[21], D8, sl))));
  ol = ffma2(cb.wf[1], D1, ffma2(cb.wf[2], D2, ffma2(cb.wf[7], D7, ffma2(cb.wf[8], D8, ol))));

  m1 = fmul2(p2, q2);
  r2 = ffma2(cb.w1[12], m1, rl);
  s2 = ffma2(cb.w1[25], m1, sl);
  ull m2 = fmul2(r2, s2);
  ull o2 = ffma2(cb.wf[12], m1, ol);
  o2 = ffma2(cb.wf[13], m2, o2);

  float ua0, ua1;
  unpk2(o2, ua0, ua1);

  const int h = h0 + ty, w = w0_ + tx;
  const size_t i0 = ((size_t)(b*2))*HH*HH + (size_t)h*HH + w;
  out[i0]         = ub[i0]         + coef*ua0;
  out[i0 + HH*HH] = ub[i0 + HH*HH] + coef*ua1;
}

extern "C" void kernel_launch(void* const* d_in, const int* in_sizes, int n_in,
                              void* d_out, int out_size)
{
  (void)in_sizes; (void)n_in; (void)out_size;
  const float* init = (const float*)d_in[0];
  const float* kern = (const float*)d_in[1];
  const float* w0   = (const float*)d_in[2];
  const float* b0   = (const float*)d_in[3];
  const float* w1   = (const float*)d_in[4];
  const float* b1   = (const float*)d_in[5];
  const float* wf   = (const float*)d_in[6];
  const float* bf   = (const float*)d_in[7];
  float* out = (float*)d_out;

  void *puh, *pua, *pub, *pstage;
  cudaGetSymbolAddress(&puh, g_uh);
  cudaGetSymbolAddress(&pua, g_ua);
  cudaGetSymbolAddress(&pub, g_ub);
  cudaGetSymbolAddress(&pstage, g_stage);

  prep_kernel<<<1, 256>>>(kern, w0, b0, w1, b1, wf, bf);
  cudaMemcpyToSymbolAsync(cb, pstage, sizeof(ConstBlob), 0, cudaMemcpyDeviceToDevice, 0);

  dim3 grid(HH/32, HH/6, BB);
  dim3 block(32, 6);

  const float DT = 0.2f;
  const float* ucur = init;
  for (int s = 0; s < 5; s++) {
    float* un = (s == 4) ? out : ((s & 1) ? (float*)pub : (float*)pua);
    rhs_step<<<grid, block>>>(ucur, ucur, DT*0.5f, (float*)puh);
    rhs_step<<<grid, block>>>((float*)puh, ucur, DT, un);
    ucur = un;
  }
}

// round 5
// speedup vs baseline: 3.0628x; 1.0220x over previous
#include <cuda_runtime.h>

typedef unsigned long long ull;

#define HH 192
#define BB 16
#define NPIX (BB*2*HH*HH)

// ---------- packed f32x2 helpers (sm_103a) ----------
__device__ __forceinline__ ull pk2(float x, float y){ ull r; asm("mov.b64 %0,{%1,%2};":"=l"(r):"f"(x),"f"(y)); return r; }
__device__ __forceinline__ ull dup2(float x){ return pk2(x,x); }
__device__ __forceinline__ void unpk2(ull v, float&x, float&y){ asm("mov.b64 {%0,%1},%2;":"=f"(x),"=f"(y):"l"(v)); }
__device__ __forceinline__ ull ffma2(ull a, ull b, ull c){ ull d; asm("fma.rn.f32x2 %0,%1,%2,%3;":"=l"(d):"l"(a),"l"(b),"l"(c)); return d; }
__device__ __forceinline__ ull fmul2(ull a, ull b){ ull d; asm("mul.rn.f32x2 %0,%1,%2;":"=l"(d):"l"(a),"l"(b)); return d; }
__device__ __forceinline__ ull fadd2(ull a, ull b){ ull d; asm("add.rn.f32x2 %0,%1,%2;":"=l"(d):"l"(a),"l"(b)); return d; }

// ---------- packed constants, 16B-vectorized ----------
// Each ull is a packed (lane0,lane1) f32x2 value. ulonglong2 packs two of
// those so a single LDCU.128 feeds two accumulators.
// kp[p][i*5+j] = ( stencil 2p tap(i,j), stencil 2p+1 tap(i,j) ), stencils
// ordered (fd00,fd01,fd10,fd02,fd11,fd20), scaled by dx^-ord, lanes duplicated.
// Flipped stencils for f01/f10 reuse kp[0].y / kp[1].x at mirrored indices.
struct ConstBlob {
  ulonglong2 kp[3][25];
  ulonglong2 w0p[12];    // .x = p-functional weight(i), .y = q-functional weight(i); lanes = poly k0,k1
  ulonglong2 w1p[13];    // .x = r-functional, .y = s-functional
  ulonglong2 b01;        // .x = b0(p), .y = b0(q)
  ulonglong2 b11;        // .x = b1(r), .y = b1(s)
  ulonglong2 gw0p[2];    // [off-1]; .x = u=0 pack, .y = u=1 pack
  ulonglong2 gw1p[2];
  ull wf[14];
  ull bf;
  ull gwf[2];
};

__constant__ ConstBlob cb;
__device__ ConstBlob g_stage;
__device__ float g_uh[NPIX];
__device__ float g_ua[NPIX];
__device__ float g_ub[NPIX];

__global__ void prep_kernel(const float* __restrict__ kern,
                            const float* __restrict__ w0, const float* __restrict__ b0,
                            const float* __restrict__ w1, const float* __restrict__ b1,
                            const float* __restrict__ wf, const float* __restrict__ bf)
{
  int t = threadIdx.x;
  const double dDX = 0.0327249;
  const float s1 = (float)(1.0/dDX);
  const float s2 = (float)(1.0/(dDX*dDX));
  const float sc[6] = {1.f, s1, s1, s2, s2, s2};
  if (t < 75) {
    int p = t/25, e = t%25;          // e = i*5+j
    int d0 = 2*p, d1 = 2*p+1;
    ulonglong2 v;
    v.x = dup2(kern[d0*25 + e] * sc[d0]);
    v.y = dup2(kern[d1*25 + e] * sc[d1]);
    g_stage.kp[p][e] = v;
  }
  if (t == 0) {
    for (int i = 0; i < 12; i++) {
      ulonglong2 a;
      a.x = pk2(w0[i],      w0[24+i]);        // u=0 weight, lanes (k0,k1)
      a.y = pk2(w0[12+i],   w0[24+12+i]);     // u=1 weight
      g_stage.w0p[i] = a;
    }
    for (int i = 0; i < 13; i++) {
      ulonglong2 a;
      a.x = pk2(w1[i],      w1[26+i]);
      a.y = pk2(w1[13+i],   w1[26+13+i]);
      g_stage.w1p[i] = a;
    }
    { ulonglong2 a; a.x = pk2(b0[0], b0[2]); a.y = pk2(b0[1], b0[3]); g_stage.b01 = a; }
    { ulonglong2 a; a.x = pk2(b1[0], b1[2]); a.y = pk2(b1[1], b1[3]); g_stage.b11 = a; }
    for (int i = 0; i < 14; i++) g_stage.wf[i] = pk2(wf[i], wf[14+i]);
    g_stage.bf = pk2(bf[0], bf[1]);
    for (int o = 0; o < 2; o++) {
      ulonglong2 a, c;
      a.x = pk2(w0[1+o],      w0[24 + 7+o]);       // u=0: lane0=k0 idx(1+o), lane1=k1 idx(7+o)
      a.y = pk2(w0[12 + 1+o], w0[24 + 12 + 7+o]);  // u=1
      g_stage.gw0p[o] = a;
      c.x = pk2(w1[1+o],      w1[26 + 7+o]);
      c.y = pk2(w1[13 + 1+o], w1[26 + 13 + 7+o]);
      g_stage.gw1p[o] = c;
      g_stage.gwf[o] = pk2(wf[1+o], wf[14 + 7+o]);
    }
  }
}

// out = ubase + coef * rhs(ueval); 1 pixel/thread, 32x6 blocks, 7 blocks/SM
__global__ __launch_bounds__(192, 7)
void rhs_step(const float* __restrict__ ue, const float* __restrict__ ub,
              float coef, float* __restrict__ out)
{
  __shared__ ull tile[10][36];   // (c0,c1) packed, rows h0-2 .. h0+7

  const int tx = threadIdx.x, ty = threadIdx.y;
  const int tid = ty*32 + tx;
  const int w0_ = blockIdx.x*32, h0 = blockIdx.y*6, b = blockIdx.z;

  const float* u0 = ue + (size_t)b*2*HH*HH;
  const float* u1 = u0 + HH*HH;

  #pragma unroll
  for (int e = tid; e < 10*36; e += 192) {
    int r = e/36, c = e%36;
    int h = h0 + r - 2; if (h < 0) h += HH; if (h >= HH) h -= HH;
    int w = w0_ + c - 2; if (w < 0) w += HH; if (w >= HH) w -= HH;
    tile[r][c] = pk2(u0[h*HH+w], u1[h*HH+w]);
  }
  __syncthreads();

  // ---- 6 base correlations + 2 mirrored (constants shared via vector loads) ----
  ull a0=0ull,a1=0ull,a2=0ull,a3=0ull,a4=0ull,a5=0ull,t6=0ull,t7=0ull;
  #pragma unroll
  for (int i = 0; i < 5; i++) {
    ull w[5];
    #pragma unroll
    for (int j = 0; j < 5; j++) w[j] = tile[ty+i][tx+j];
    #pragma unroll
    for (int j = 0; j < 5; j++) {
      const ulonglong2 k01 = cb.kp[0][i*5+j];
      const ulonglong2 k23 = cb.kp[1][i*5+j];
      const ulonglong2 k45 = cb.kp[2][i*5+j];
      a0 = ffma2(k01.x, w[j], a0);
      a1 = ffma2(k01.y, w[j], a1);
      a2 = ffma2(k23.x, w[j], a2);
      a3 = ffma2(k23.y, w[j], a3);
      a4 = ffma2(k45.x, w[j], a4);
      a5 = ffma2(k45.y, w[j], a5);
      // f01 = -sum k01tap(i,j)*w(i,4-j): use current k01.y with mirrored window value
      t6 = ffma2(k01.y, w[4-j], t6);
      // f10 = -sum k10tap(i,j)*w(4-i,j): constant from row 4-i (CSE with that row's load)
      t7 = ffma2(cb.kp[1][(4-i)*5+j].x, w[j], t7);
    }
  }

  float X[12];
  unpk2(a0, X[0], X[6]); unpk2(a1, X[1], X[7]); unpk2(a2, X[2], X[8]);
  unpk2(a3, X[3], X[9]); unpk2(a4, X[4], X[10]); unpk2(a5, X[5], X[11]);
  float n6x, n6y, n7x, n7y;
  unpk2(t6, n6x, n6y);   // f01 = -n6
  unpk2(t7, n7x, n7y);   // f10 = -n7

  // ---- poly linear parts at base (lanes = poly k0,k1) ----
  ull p2 = cb.b01.x, q2 = cb.b01.y, rl = cb.b11.x, sl = cb.b11.y, ol = cb.bf;
  #pragma unroll
  for (int i = 0; i < 12; i++) {
    ull xd = dup2(X[i]);
    const ulonglong2 wa = cb.w0p[i];
    const ulonglong2 wb = cb.w1p[i];
    p2 = ffma2(wa.x, xd, p2);
    q2 = ffma2(wa.y, xd, q2);
    rl = ffma2(wb.x, xd, rl);
    sl = ffma2(wb.y, xd, sl);
    ol = ffma2(cb.wf[i], xd, ol);
  }
  const ulonglong2 wm = cb.w1p[12];   // m1 coefficients for (r,s)
  ull m1 = fmul2(p2, q2);
  ull r2 = ffma2(wm.x, m1, rl);
  ull s2 = ffma2(wm.y, m1, sl);

  // ---- analytic gradient at base: d(poly_k)/dX[k*6+off], off=1,2 ----
  ull g2[2];
  #pragma unroll
  for (int o = 0; o < 2; o++) {
    const ulonglong2 ga = cb.gw0p[o];
    const ulonglong2 gc = cb.gw1p[o];
    ull dm1 = fadd2(fmul2(q2, ga.x), fmul2(p2, ga.y));
    ull dr  = ffma2(wm.x, dm1, gc.x);
    ull ds  = ffma2(wm.y, dm1, gc.y);
    ull dm2 = fadd2(fmul2(s2, dr), fmul2(r2, ds));
    ull g   = ffma2(cb.wf[12], dm1, cb.gwf[o]);
    g2[o]   = ffma2(cb.wf[13], dm2, g);
  }
  float g01a, g01b, g10a, g10b;
  unpk2(g2[0], g01a, g01b);
  unpk2(g2[1], g10a, g10b);

  // upwind deltas (0 if keep base, else flipped - base); flipped = -n
  float d1 = (g01a > 0.f) ? 0.f : (-n6x - X[1]);
  float d7 = (g01b > 0.f) ? 0.f : (-n6y - X[7]);
  float d2 = (g10a > 0.f) ? 0.f : (-n7x - X[2]);
  float d8 = (g10b > 0.f) ? 0.f : (-n7y - X[8]);
  ull D1 = dup2(d1), D2 = dup2(d2), D7 = dup2(d7), D8 = dup2(d8);

  // ---- delta-update linear parts to Xsel, finish poly ----
  {
    const ulonglong2 c1 = cb.w0p[1], c2 = cb.w0p[2], c7 = cb.w0p[7], c8 = cb.w0p[8];
    p2 = ffma2(c1.x, D1, ffma2(c2.x, D2, ffma2(c7.x, D7, ffma2(c8.x, D8, p2))));
    q2 = ffma2(c1.y, D1, ffma2(c2.y, D2, ffma2(c7.y, D7, ffma2(c8.y, D8, q2))));
  }
  {
    const ulonglong2 c1 = cb.w1p[1], c2 = cb.w1p[2], c7 = cb.w1p[7], c8 = cb.w1p[8];
    rl = ffma2(c1.x, D1, ffma2(c2.x, D2, ffma2(c7.x, D7, ffma2(c8.x, D8, rl))));
    sl = ffma2(c1.y, D1, ffma2(c2.y, D2, ffma2(c7.y, D7, ffma2(c8.y, D8, sl))));
  }
  ol = ffma2(cb.wf[1], D1, ffma2(cb.wf[2], D2, ffma2(cb.wf[7], D7, ffma2(cb.wf[8], D8, ol))));

  m1 = fmul2(p2, q2);
  r2 = ffma2(wm.x, m1, rl);
  s2 = ffma2(wm.y, m1, sl);
  ull m2 = fmul2(r2, s2);
  ull o2 = ffma2(cb.wf[12], m1, ol);
  o2 = ffma2(cb.wf[13], m2, o2);

  float ua0, ua1;
  unpk2(o2, ua0, ua1);

  const int h = h0 + ty, w = w0_ + tx;
  const size_t i0 = ((size_t)(b*2))*HH*HH + (size_t)h*HH + w;
  out[i0]         = ub[i0]         + coef*ua0;
  out[i0 + HH*HH] = ub[i0 + HH*HH] + coef*ua1;
}

extern "C" void kernel_launch(void* const* d_in, const int* in_sizes, int n_in,
                              void* d_out, int out_size)
{
  (void)in_sizes; (void)n_in; (void)out_size;
  const float* init = (const float*)d_in[0];
  const float* kern = (const float*)d_in[1];
  const float* w0   = (const float*)d_in[2];
  const float* b0   = (const float*)d_in[3];
  const float* w1   = (const float*)d_in[4];
  const float* b1   = (const float*)d_in[5];
  const float* wf   = (const float*)d_in[6];
  const float* bf   = (const float*)d_in[7];
  float* out = (float*)d_out;

  void *puh, *pua, *pub, *pstage;
  cudaGetSymbolAddress(&puh, g_uh);
  cudaGetSymbolAddress(&pua, g_ua);
  cudaGetSymbolAddress(&pub, g_ub);
  cudaGetSymbolAddress(&pstage, g_stage);

  prep_kernel<<<1, 128>>>(kern, w0, b0, w1, b1, wf, bf);
  cudaMemcpyToSymbolAsync(cb, pstage, sizeof(ConstBlob), 0, cudaMemcpyDeviceToDevice, 0);

  dim3 grid(HH/32, HH/6, BB);
  dim3 block(32, 6);

  const float DT = 0.2f;
  const float* ucur = init;
  for (int s = 0; s < 5; s++) {
    float* un = (s == 4) ? out : ((s & 1) ? (float*)pub : (float*)pua);
    rhs_step<<<grid, block>>>(ucur, ucur, DT*0.5f, (float*)puh);
    rhs_step<<<grid, block>>>((float*)puh, ucur, DT, un);
    ucur = un;
  }
}